// round 6
// baseline (speedup 1.0000x reference)
#include <cuda_runtime.h>

#define BB 4096
#define TT 1024
#define NN 16
#define NPT 2   // packed pairs per thread: 4 threads/row * 2 pairs * 2 = 16 filters

// Transposed currents scratch: [T+8][B] (8 rows prefetch-overrun padding).
__device__ float g_curT[(TT + 8) * BB];

typedef unsigned long long u64;

__device__ __forceinline__ u64 pk2(float x, float y) {
    u64 r; asm("mov.b64 %0, {%1, %2};" : "=l"(r) : "f"(x), "f"(y)); return r;
}
__device__ __forceinline__ void upk2(u64 a, float& x, float& y) {
    asm("mov.b64 {%0, %1}, %2;" : "=f"(x), "=f"(y) : "l"(a));
}
__device__ __forceinline__ u64 fma2_(u64 a, u64 b, u64 c) {
    u64 d; asm("fma.rn.f32x2 %0, %1, %2, %3;" : "=l"(d) : "l"(a), "l"(b), "l"(c)); return d;
}
__device__ __forceinline__ u64 mul2_(u64 a, u64 b) {
    u64 d; asm("mul.rn.f32x2 %0, %1, %2;" : "=l"(d) : "l"(a), "l"(b)); return d;
}
__device__ __forceinline__ u64 add2_(u64 a, u64 b) {
    u64 d; asm("add.rn.f32x2 %0, %1, %2;" : "=l"(d) : "l"(a), "l"(b)); return d;
}
__device__ __forceinline__ float tanh_a(float x) {
    float y; asm("tanh.approx.f32 %0, %1;" : "=f"(y) : "f"(x)); return y;
}

// ---------------------------------------------------------------------------
// Pass 1: transpose currents (B,T) -> g_curT (T,B).
// ---------------------------------------------------------------------------
__global__ void transpose_kernel(const float* __restrict__ cur) {
    __shared__ float tile[32][33];
    const int tx = threadIdx.x, ty = threadIdx.y;
    const int t0 = blockIdx.x * 32, b0 = blockIdx.y * 32;
#pragma unroll
    for (int i = 0; i < 32; i += 8)
        tile[ty + i][tx] = cur[(size_t)(b0 + ty + i) * TT + (t0 + tx)];
    __syncthreads();
#pragma unroll
    for (int i = 0; i < 32; i += 8)
        g_curT[(size_t)(t0 + ty + i) * BB + (b0 + tx)] = tile[tx][ty + i];
}

// ---------------------------------------------------------------------------
// Pass 2: recurrence. FOUR threads per batch row; each owns 4 filters
// (2 packed f32x2 pairs). 128 blocks x 128 threads: 1 block/SM, 1 warp/SMSP.
//
// KEY FIX vs R5: the loop body is now 100% BRANCH-FREE. The per-step
// `if (sub==0)` store guard compiled to a BSSY/BSYNC divergence envelope
// (~33-56+ cyc EVERY step — ptxas never predicates C++ if{}). All four
// lanes of a row compute the identical thn, so all four store the same
// value to the same address; the warp's store unit merges them.
//
// Carried variable th (fs = MFR*th; MFR folded into b coeffs + output).
// relu∘(MFR·tanh) == MFR·tanh∘relu (exact, MFR>0).
// ---------------------------------------------------------------------------
__global__ void __launch_bounds__(128, 1) gfr_kernel(
    const float* __restrict__ a, const float* __restrict__ b,
    const float* __restrict__ pc, const float* __restrict__ gb,
    const float* __restrict__ ds, const float* __restrict__ mc,
    const float* __restrict__ mfr, float* __restrict__ out)
{
    const int tid = threadIdx.x;
    const int sub = tid & 3;                         // lane within row-group
    const int row = blockIdx.x * 32 + (tid >> 2);    // batch row
    const int f0  = sub * 4;                         // first filter index

    const float MFR = mfr[0];
    const float invmc = 1.f / mc[0];
    const float csN = invmc * (1.f / (float)NN);

    u64 av[NPT], bv[NPT], dv[NPT], v[NPT];
#pragma unroll
    for (int i = 0; i < NPT; i++) {
        av[i] = pk2(a[f0 + 2 * i], a[f0 + 2 * i + 1]);
        bv[i] = pk2(1000.f * MFR * b[f0 + 2 * i], 1000.f * MFR * b[f0 + 2 * i + 1]);
        dv[i] = pk2(1.f - ds[f0 + 2 * i], 1.f - ds[f0 + 2 * i + 1]);
        v[i] = 0ull;
    }
    // full-sum constants over ALL 16 filters
    float suma = 0.f, sumb = 0.f;
#pragma unroll
    for (int n = 0; n < NN; n++) { suma += a[n]; sumb += b[n]; }
    const float ca = suma * csN;                 // currents feed-through
    const float cb = 1000.f * MFR * sumb * csN;  // th feedback
    const float c0 = -gb[0] * invmc;
    const float q0 = pc[0] * pc[0], q1 = pc[1] * pc[1], q2 = pc[2] * pc[2],
                q3 = pc[3] * pc[3], q4 = pc[4] * pc[4];

    const float* cp = g_curT + row;
    float* op = out + row;
    float th = 0.f;

    constexpr int PF = 8;
    float curbuf[PF];
#pragma unroll
    for (int i = 0; i < PF; i++) curbuf[i] = __ldg(cp + (size_t)i * BB);

    for (int t = 0; t < TT; t += PF) {
#pragma unroll
        for (int j = 0; j < PF; j++) {
            const float cur = curbuf[j];                         // PF-steps old
            curbuf[j] = __ldg(cp + (size_t)(t + j + PF) * BB);   // not consumed here
            const float pre = fmaf(cur, ca, c0);                 // off critical path

            // w = decay * v  (reused for v update)
            u64 w0 = mul2_(dv[0], v[0]);
            u64 w1 = mul2_(dv[1], v[1]);

            // own partial sum (4 filters)
            u64 s = add2_(w0, w1);
            float sx, sy; upk2(s, sx, sy);
            const float Wp = sx + sy;

            // 3 parallel shuffles: all partner partials at once
            const float A  = __shfl_xor_sync(0xFFFFFFFFu, Wp, 1);
            const float Bx = __shfl_xor_sync(0xFFFFFFFFu, Wp, 2);
            const float C  = __shfl_xor_sync(0xFFFFFFFFu, Wp, 3);
            const float W = (Wp + A) + (Bx + C);

            const float base = fmaf(W, csN, pre);
            // ---- th critical path ----
            const float x = fmaf(th, cb, base);
            const float x2 = x * x;
            const float u01 = fmaf(q1, x, q0);
            const float u34 = fmaf(q4, x, q3);
            const float w1s = fmaf(q2, x2, u01);
            const float x3 = x * x2;
            float p = fmaf(u34, x3, w1s);
            p = fmaxf(p, 0.f);
            const float thn = tanh_a(p);
            // --------------------------

            // v_t = w + cur*a + (OLD th)*bM
            const u64 curp2 = pk2(cur, cur);
            const u64 thp2  = pk2(th, th);
            v[0] = fma2_(curp2, av[0], fma2_(thp2, bv[0], w0));
            v[1] = fma2_(curp2, av[1], fma2_(thp2, bv[1], w1));

            // BRANCH-FREE store: all 4 lanes write the identical value to the
            // same address; the warp store unit merges them (8 unique words).
            op[(size_t)(t + j) * BB] = MFR * thn;
            th = thn;
        }
    }
}

extern "C" void kernel_launch(void* const* d_in, const int* in_sizes, int n_in,
                              void* d_out, int out_size) {
    const float* currents = (const float*)d_in[0];
    const float* a   = (const float*)d_in[1];
    const float* b   = (const float*)d_in[2];
    const float* pc  = (const float*)d_in[3];
    const float* gb  = (const float*)d_in[4];
    const float* ds  = (const float*)d_in[5];
    const float* mc  = (const float*)d_in[6];
    const float* mfr = (const float*)d_in[7];
    float* out = (float*)d_out;

    dim3 tb(32, 8), tg(TT / 32, BB / 32);
    transpose_kernel<<<tg, tb>>>(currents);
    // 4 threads/row: 16384 threads = 128 blocks x 128 -> 1 block/SM, 1 warp/SMSP
    gfr_kernel<<<(4 * BB) / 128, 128>>>(a, b, pc, gb, ds, mc, mfr, out);
}

// round 7
// speedup vs baseline: 1.2200x; 1.2200x over previous
#include <cuda_runtime.h>

#define BB 4096
#define TT 1024
#define NN 16
#define NPT 2   // packed pairs per thread: 4 threads/row * 2 pairs * 2 = 16 filters
#define TQ (TT / 4)

// Quad-packed transposed currents: g_cur4[tq][b] = {cur[4tq..4tq+3]} for row b.
// +4 quads of padding for prefetch overrun.
__device__ float4 g_cur4[(TQ + 4) * BB];

typedef unsigned long long u64;

__device__ __forceinline__ u64 pk2(float x, float y) {
    u64 r; asm("mov.b64 %0, {%1, %2};" : "=l"(r) : "f"(x), "f"(y)); return r;
}
__device__ __forceinline__ void upk2(u64 a, float& x, float& y) {
    asm("mov.b64 {%0, %1}, %2;" : "=f"(x), "=f"(y) : "l"(a));
}
__device__ __forceinline__ u64 fma2_(u64 a, u64 b, u64 c) {
    u64 d; asm("fma.rn.f32x2 %0, %1, %2, %3;" : "=l"(d) : "l"(a), "l"(b), "l"(c)); return d;
}
__device__ __forceinline__ u64 mul2_(u64 a, u64 b) {
    u64 d; asm("mul.rn.f32x2 %0, %1, %2;" : "=l"(d) : "l"(a), "l"(b)); return d;
}
__device__ __forceinline__ u64 add2_(u64 a, u64 b) {
    u64 d; asm("add.rn.f32x2 %0, %1, %2;" : "=l"(d) : "l"(a), "l"(b)); return d;
}
__device__ __forceinline__ float tanh_a(float x) {
    float y; asm("tanh.approx.f32 %0, %1;" : "=f"(y) : "f"(x)); return y;
}

// ---------------------------------------------------------------------------
// Pass 1: transpose + quad-pack currents (B,T) -> g_cur4 (T/4, B) float4.
// ---------------------------------------------------------------------------
__global__ void transpose_kernel(const float* __restrict__ cur) {
    __shared__ float tile[32][33];
    const int tx = threadIdx.x, ty = threadIdx.y;
    const int t0 = blockIdx.x * 32, b0 = blockIdx.y * 32;
#pragma unroll
    for (int i = 0; i < 32; i += 8)
        tile[ty + i][tx] = cur[(size_t)(b0 + ty + i) * TT + (t0 + tx)];
    __syncthreads();
    // thread (tx,ty): row b = b0+tx, quad = t0/4 + ty (ty=0..7 covers 32 t)
    float4 val;
    val.x = tile[tx][4 * ty + 0];
    val.y = tile[tx][4 * ty + 1];
    val.z = tile[tx][4 * ty + 2];
    val.w = tile[tx][4 * ty + 3];
    g_cur4[(size_t)((t0 >> 2) + ty) * BB + (b0 + tx)] = val;
}

// ---------------------------------------------------------------------------
// Pass 2: recurrence. FOUR threads per row, 4 filters each (2 packed pairs).
// 128 blocks x 128 threads: 1 block/SM, 1 warp/SMSP.
//
// KEY CHANGES vs R6 (memory-op thinning):
//  * one LDG.128 per 4 steps (quad-packed currents), 2 quads in flight ->
//    scoreboard slot-reuse distance ~8 steps (>450 cyc) >> L2 latency, so no
//    per-step exposed memory wait (with 1 LDG/step + 6 SB slots the reuse
//    distance was ~4-5 steps ~ L2 latency: a recurring partial stall).
//  * one STG.32 per 4 steps per lane: lane sub keeps timestep 4k+sub's
//    output via compile-time SEL (values are replicated across the 4 lanes).
//  * v-state pre-scaled by csN: base = W + pre (FADD), one less chain FMA.
// ---------------------------------------------------------------------------
__global__ void __launch_bounds__(128, 1) gfr_kernel(
    const float* __restrict__ a, const float* __restrict__ b,
    const float* __restrict__ pc, const float* __restrict__ gb,
    const float* __restrict__ ds, const float* __restrict__ mc,
    const float* __restrict__ mfr, float* __restrict__ out)
{
    const int tid = threadIdx.x;
    const int sub = tid & 3;
    const int row = blockIdx.x * 32 + (tid >> 2);
    const int f0  = sub * 4;

    const float MFR = mfr[0];
    const float invmc = 1.f / mc[0];
    const float csN = invmc * (1.f / (float)NN);

    u64 av[NPT], bv[NPT], dv[NPT], v[NPT];
#pragma unroll
    for (int i = 0; i < NPT; i++) {
        // csN folded into the state scale (v' = csN * v)
        av[i] = pk2(csN * a[f0 + 2 * i], csN * a[f0 + 2 * i + 1]);
        bv[i] = pk2(csN * 1000.f * MFR * b[f0 + 2 * i],
                    csN * 1000.f * MFR * b[f0 + 2 * i + 1]);
        dv[i] = pk2(1.f - ds[f0 + 2 * i], 1.f - ds[f0 + 2 * i + 1]);
        v[i] = 0ull;
    }
    float suma = 0.f, sumb = 0.f;
#pragma unroll
    for (int n = 0; n < NN; n++) { suma += a[n]; sumb += b[n]; }
    const float ca = suma * csN;
    const float cb = 1000.f * MFR * sumb * csN;
    const float c0 = -gb[0] * invmc;
    const float q0 = pc[0] * pc[0], q1 = pc[1] * pc[1], q2 = pc[2] * pc[2],
                q3 = pc[3] * pc[3], q4 = pc[4] * pc[4];

    const float4* cp4 = g_cur4 + row;
    float* op = out + row + (size_t)sub * BB;  // lane sub owns timestep 4k+sub
    float th = 0.f;

    float4 q0buf = __ldg(cp4);
    float4 q1buf = __ldg(cp4 + BB);

#define STEP(CUR, J)                                                        \
    {                                                                       \
        const float cur_ = (CUR);                                           \
        const float pre_ = fmaf(cur_, ca, c0);                              \
        u64 w0 = mul2_(dv[0], v[0]);                                        \
        u64 w1 = mul2_(dv[1], v[1]);                                        \
        u64 s_ = add2_(w0, w1);                                             \
        float sx_, sy_; upk2(s_, sx_, sy_);                                 \
        const float Wp_ = sx_ + sy_;                                        \
        const float A_  = __shfl_xor_sync(0xFFFFFFFFu, Wp_, 1);             \
        const float B_  = __shfl_xor_sync(0xFFFFFFFFu, Wp_, 2);             \
        const float C_  = __shfl_xor_sync(0xFFFFFFFFu, Wp_, 3);             \
        const float W_  = (Wp_ + A_) + (B_ + C_);                           \
        const float base_ = W_ + pre_;                                      \
        const float x_ = fmaf(th, cb, base_);                               \
        const float x2_ = x_ * x_;                                          \
        const float u01_ = fmaf(q1, x_, q0);                                \
        const float u34_ = fmaf(q4, x_, q3);                                \
        const float w1s_ = fmaf(q2, x2_, u01_);                             \
        const float x3_ = x_ * x2_;                                         \
        float p_ = fmaf(u34_, x3_, w1s_);                                   \
        p_ = fmaxf(p_, 0.f);                                                \
        const float thn_ = tanh_a(p_);                                      \
        const u64 curp2_ = pk2(cur_, cur_);                                 \
        const u64 thp2_  = pk2(th, th);                                     \
        v[0] = fma2_(curp2_, av[0], fma2_(thp2_, bv[0], w0));               \
        v[1] = fma2_(curp2_, av[1], fma2_(thp2_, bv[1], w1));               \
        if ((J) == sub) outv = MFR * thn_;  /* compile-time J -> SEL */     \
        th = thn_;                                                          \
    }

    for (int tq = 0; tq < TQ; tq += 2) {
        float outv = 0.f;
        {
            const float4 q = q0buf;
            q0buf = __ldg(cp4 + (size_t)(tq + 2) * BB);
            STEP(q.x, 0) STEP(q.y, 1) STEP(q.z, 2) STEP(q.w, 3)
            op[(size_t)tq * (4 * BB)] = outv;
        }
        {
            const float4 q = q1buf;
            q1buf = __ldg(cp4 + (size_t)(tq + 3) * BB);
            STEP(q.x, 0) STEP(q.y, 1) STEP(q.z, 2) STEP(q.w, 3)
            op[(size_t)(tq + 1) * (4 * BB)] = outv;
        }
    }
#undef STEP
}

extern "C" void kernel_launch(void* const* d_in, const int* in_sizes, int n_in,
                              void* d_out, int out_size) {
    const float* currents = (const float*)d_in[0];
    const float* a   = (const float*)d_in[1];
    const float* b   = (const float*)d_in[2];
    const float* pc  = (const float*)d_in[3];
    const float* gb  = (const float*)d_in[4];
    const float* ds  = (const float*)d_in[5];
    const float* mc  = (const float*)d_in[6];
    const float* mfr = (const float*)d_in[7];
    float* out = (float*)d_out;

    dim3 tb(32, 8), tg(TT / 32, BB / 32);
    transpose_kernel<<<tg, tb>>>(currents);
    gfr_kernel<<<(4 * BB) / 128, 128>>>(a, b, pc, gb, ds, mc, mfr, out);
}

// round 8
// speedup vs baseline: 1.2548x; 1.0285x over previous
#include <cuda_runtime.h>

#define BB 4096
#define TT 1024
#define NN 16
#define NF 4    // filters per thread: 4 threads/row * 4 = 16
#define TQ (TT / 4)

// Quad-packed transposed currents: g_cur4[tq][b] = {cur[4tq..4tq+3]} for row b.
// +4 quads of padding for prefetch overrun.
__device__ float4 g_cur4[(TQ + 4) * BB];

__device__ __forceinline__ float tanh_a(float x) {
    float y; asm("tanh.approx.f32 %0, %1;" : "=f"(y) : "f"(x)); return y;
}

// ---------------------------------------------------------------------------
// Pass 1: transpose + quad-pack currents (B,T) -> g_cur4 (T/4, B) float4.
// ---------------------------------------------------------------------------
__global__ void transpose_kernel(const float* __restrict__ cur) {
    __shared__ float tile[32][33];
    const int tx = threadIdx.x, ty = threadIdx.y;
    const int t0 = blockIdx.x * 32, b0 = blockIdx.y * 32;
#pragma unroll
    for (int i = 0; i < 32; i += 8)
        tile[ty + i][tx] = cur[(size_t)(b0 + ty + i) * TT + (t0 + tx)];
    __syncthreads();
    float4 val;
    val.x = tile[tx][4 * ty + 0];
    val.y = tile[tx][4 * ty + 1];
    val.z = tile[tx][4 * ty + 2];
    val.w = tile[tx][4 * ty + 3];
    g_cur4[(size_t)((t0 >> 2) + ty) * BB + (b0 + tx)] = val;
}

// ---------------------------------------------------------------------------
// Pass 2: recurrence. FOUR threads per row, 4 filters each — ALL SCALAR math.
//
// KEY CHANGE vs R7: zero f32x2 packed ops. fma.rn.f32x2's latency is absent
// from the measured latency tables (only FFMA lat=4/rt=2 is documented);
// the ~100cyc/step unexplained excess survived shuffle removal (R1) and is
// common only to the packed datapath. Scalar FFMA/FMUL/FADD have known
// lat 4 / rt 2 and avoid register-pair marshalling + RF-bank rt inflation
// (packed ops read 6 distinct registers -> rt >= 3 by bank rule).
//
// Everything else kept from R7: quad LDG (1 per 4 steps), lane-owned quad
// output (1 STG.32 per 4 steps), 3 parallel shfl_xor, branch-free body,
// csN folded into state scale, th-carried variable, tanh∘relu refactor.
// ---------------------------------------------------------------------------
__global__ void __launch_bounds__(128, 1) gfr_kernel(
    const float* __restrict__ a, const float* __restrict__ b,
    const float* __restrict__ pc, const float* __restrict__ gb,
    const float* __restrict__ ds, const float* __restrict__ mc,
    const float* __restrict__ mfr, float* __restrict__ out)
{
    const int tid = threadIdx.x;
    const int sub = tid & 3;
    const int row = blockIdx.x * 32 + (tid >> 2);
    const int f0  = sub * NF;

    const float MFR = mfr[0];
    const float invmc = 1.f / mc[0];
    const float csN = invmc * (1.f / (float)NN);

    // per-thread filter constants, csN folded into the state scale
    float af[NF], bf[NF], df[NF], v0f, v1f, v2f, v3f;
#pragma unroll
    for (int i = 0; i < NF; i++) {
        af[i] = csN * a[f0 + i];
        bf[i] = csN * 1000.f * MFR * b[f0 + i];
        df[i] = 1.f - ds[f0 + i];
    }
    v0f = v1f = v2f = v3f = 0.f;

    float suma = 0.f, sumb = 0.f;
#pragma unroll
    for (int n = 0; n < NN; n++) { suma += a[n]; sumb += b[n]; }
    const float ca = suma * csN;
    const float cb = 1000.f * MFR * sumb * csN;
    const float c0 = -gb[0] * invmc;
    const float q0 = pc[0] * pc[0], q1 = pc[1] * pc[1], q2 = pc[2] * pc[2],
                q3 = pc[3] * pc[3], q4 = pc[4] * pc[4];

    const float4* cp4 = g_cur4 + row;
    float* op = out + row + (size_t)sub * BB;  // lane sub owns timestep 4k+sub
    float th = 0.f;

    float4 q0buf = __ldg(cp4);
    float4 q1buf = __ldg(cp4 + BB);

#define STEP(CUR, J)                                                        \
    {                                                                       \
        const float cur_ = (CUR);                                           \
        const float pre_ = fmaf(cur_, ca, c0);                              \
        const float w0_ = df[0] * v0f;                                      \
        const float w1_ = df[1] * v1f;                                      \
        const float w2_ = df[2] * v2f;                                      \
        const float w3_ = df[3] * v3f;                                      \
        const float Wp_ = (w0_ + w1_) + (w2_ + w3_);                        \
        const float A_  = __shfl_xor_sync(0xFFFFFFFFu, Wp_, 1);             \
        const float B_  = __shfl_xor_sync(0xFFFFFFFFu, Wp_, 2);             \
        const float C_  = __shfl_xor_sync(0xFFFFFFFFu, Wp_, 3);             \
        const float W_  = (Wp_ + A_) + (B_ + C_);                           \
        const float base_ = W_ + pre_;                                      \
        const float x_ = fmaf(th, cb, base_);                               \
        const float x2_ = x_ * x_;                                          \
        const float u01_ = fmaf(q1, x_, q0);                                \
        const float u34_ = fmaf(q4, x_, q3);                                \
        const float w1s_ = fmaf(q2, x2_, u01_);                             \
        const float x3_ = x_ * x2_;                                         \
        float p_ = fmaf(u34_, x3_, w1s_);                                   \
        p_ = fmaxf(p_, 0.f);                                                \
        const float thn_ = tanh_a(p_);                                      \
        v0f = fmaf(cur_, af[0], fmaf(th, bf[0], w0_));                      \
        v1f = fmaf(cur_, af[1], fmaf(th, bf[1], w1_));                      \
        v2f = fmaf(cur_, af[2], fmaf(th, bf[2], w2_));                      \
        v3f = fmaf(cur_, af[3], fmaf(th, bf[3], w3_));                      \
        if ((J) == sub) outv = MFR * thn_;  /* compile-time J -> SEL */     \
        th = thn_;                                                          \
    }

    for (int tq = 0; tq < TQ; tq += 2) {
        float outv = 0.f;
        {
            const float4 q = q0buf;
            q0buf = __ldg(cp4 + (size_t)(tq + 2) * BB);
            STEP(q.x, 0) STEP(q.y, 1) STEP(q.z, 2) STEP(q.w, 3)
            op[(size_t)tq * (4 * BB)] = outv;
        }
        {
            const float4 q = q1buf;
            q1buf = __ldg(cp4 + (size_t)(tq + 3) * BB);
            STEP(q.x, 0) STEP(q.y, 1) STEP(q.z, 2) STEP(q.w, 3)
            op[(size_t)(tq + 1) * (4 * BB)] = outv;
        }
    }
#undef STEP
}

extern "C" void kernel_launch(void* const* d_in, const int* in_sizes, int n_in,
                              void* d_out, int out_size) {
    const float* currents = (const float*)d_in[0];
    const float* a   = (const float*)d_in[1];
    const float* b   = (const float*)d_in[2];
    const float* pc  = (const float*)d_in[3];
    const float* gb  = (const float*)d_in[4];
    const float* ds  = (const float*)d_in[5];
    const float* mc  = (const float*)d_in[6];
    const float* mfr = (const float*)d_in[7];
    float* out = (float*)d_out;

    dim3 tb(32, 8), tg(TT / 32, BB / 32);
    transpose_kernel<<<tg, tb>>>(currents);
    gfr_kernel<<<(4 * BB) / 128, 128>>>(a, b, pc, gb, ds, mc, mfr, out);
}

// round 9
// speedup vs baseline: 1.4544x; 1.1591x over previous
#include <cuda_runtime.h>

#define BB 4096
#define TT 1024
#define NN 16
#define NPT 2   // packed pairs per thread: 4 threads/row * 2 pairs * 2 = 16 filters
#define TQ (TT / 4)

// Quad-packed transposed currents: g_cur4[tq][b] = {cur[4tq..4tq+3]} for row b.
__device__ float4 g_cur4[(TQ + 4) * BB];

typedef unsigned long long u64;

__device__ __forceinline__ u64 pk2(float x, float y) {
    u64 r; asm("mov.b64 %0, {%1, %2};" : "=l"(r) : "f"(x), "f"(y)); return r;
}
__device__ __forceinline__ void upk2(u64 a, float& x, float& y) {
    asm("mov.b64 {%0, %1}, %2;" : "=f"(x), "=f"(y) : "l"(a));
}
__device__ __forceinline__ u64 fma2_(u64 a, u64 b, u64 c) {
    u64 d; asm("fma.rn.f32x2 %0, %1, %2, %3;" : "=l"(d) : "l"(a), "l"(b), "l"(c)); return d;
}
__device__ __forceinline__ u64 mul2_(u64 a, u64 b) {
    u64 d; asm("mul.rn.f32x2 %0, %1, %2;" : "=l"(d) : "l"(a), "l"(b)); return d;
}
__device__ __forceinline__ float tanh_a(float x) {
    float y; asm("tanh.approx.f32 %0, %1;" : "=f"(y) : "f"(x)); return y;
}

// ---------------------------------------------------------------------------
// Pass 1: transpose + quad-pack currents (B,T) -> g_cur4 (T/4, B) float4.
// ---------------------------------------------------------------------------
__global__ void transpose_kernel(const float* __restrict__ cur) {
    __shared__ float tile[32][33];
    const int tx = threadIdx.x, ty = threadIdx.y;
    const int t0 = blockIdx.x * 32, b0 = blockIdx.y * 32;
#pragma unroll
    for (int i = 0; i < 32; i += 8)
        tile[ty + i][tx] = cur[(size_t)(b0 + ty + i) * TT + (t0 + tx)];
    __syncthreads();
    float4 val;
    val.x = tile[tx][4 * ty + 0];
    val.y = tile[tx][4 * ty + 1];
    val.z = tile[tx][4 * ty + 2];
    val.w = tile[tx][4 * ty + 3];
    g_cur4[(size_t)((t0 >> 2) + ty) * BB + (b0 + tx)] = val;
}

// ---------------------------------------------------------------------------
// Pass 2: recurrence with a MOMENT PIPELINE that takes the cross-lane
// reduction off the per-step critical path.
//
//   M_k[t] = sum_i d_i^k V_i[t]  satisfies (exact algebra):
//     M_1[t] = M_2[t-1] + cur_t*a1c + th[t-1]*b1c
//     M_2[t] = M_3[t-1] + cur_t*a2c + th[t-1]*b2c
//     M_3[t-1] = sum_i d_i^3 V_i[t-1]   <- the ONLY shuffle reduction
//
//   x[t] = fma(th[t-1], cb, M_1[t-1] + pre_t).
//
// The shuffle result M_3[t-1] is consumed via M_2[t] -> M_1[t+1] -> x[t+2]:
// ~2.5 steps (~90+ cyc) of slack vs ~50 cyc reduction latency. The per-step
// critical chain is now pure th->th: FMA + Estrin + FMNMX + MUFU.TANH ~ 36cyc.
//
// Filters packed f32x2 again (R8 exonerated packed ops; halves issue count).
// Quad LDG / lane-owned quad STG / branch-free body kept from R7/R8.
// ---------------------------------------------------------------------------
__global__ void __launch_bounds__(128, 1) gfr_kernel(
    const float* __restrict__ a, const float* __restrict__ b,
    const float* __restrict__ pc, const float* __restrict__ gb,
    const float* __restrict__ ds, const float* __restrict__ mc,
    const float* __restrict__ mfr, float* __restrict__ out)
{
    const int tid = threadIdx.x;
    const int sub = tid & 3;
    const int row = blockIdx.x * 32 + (tid >> 2);
    const int f0  = sub * 4;

    const float MFR = mfr[0];
    const float invmc = 1.f / mc[0];
    const float csN = invmc * (1.f / (float)NN);

    // per-lane packed filter constants (state pre-scaled by csN)
    u64 av[NPT], bv[NPT], dv[NPT], d3v[NPT], v[NPT];
#pragma unroll
    for (int i = 0; i < NPT; i++) {
        const float dA = 1.f - ds[f0 + 2 * i], dB = 1.f - ds[f0 + 2 * i + 1];
        av[i]  = pk2(csN * a[f0 + 2 * i], csN * a[f0 + 2 * i + 1]);
        bv[i]  = pk2(csN * 1000.f * MFR * b[f0 + 2 * i],
                     csN * 1000.f * MFR * b[f0 + 2 * i + 1]);
        dv[i]  = pk2(dA, dB);
        d3v[i] = pk2(dA * dA * dA, dB * dB * dB);
        v[i] = 0ull;
    }
    // global sums over ALL 16 filters
    float suma = 0.f, sumb = 0.f, a1c = 0.f, b1c = 0.f, a2c = 0.f, b2c = 0.f;
#pragma unroll
    for (int n = 0; n < NN; n++) {
        const float dn = 1.f - ds[n];
        const float An = csN * a[n];
        const float Bn = csN * 1000.f * MFR * b[n];
        suma += a[n]; sumb += b[n];
        a1c += dn * An;        b1c += dn * Bn;
        a2c += dn * dn * An;   b2c += dn * dn * Bn;
    }
    const float ca = suma * csN;
    const float cb = 1000.f * MFR * sumb * csN;
    const float c0 = -gb[0] * invmc;
    const float q0 = pc[0] * pc[0], q1 = pc[1] * pc[1], q2 = pc[2] * pc[2],
                q3 = pc[3] * pc[3], q4 = pc[4] * pc[4];

    const float4* cp4 = g_cur4 + row;
    float* op = out + row + (size_t)sub * BB;
    float th = 0.f, M1 = 0.f, M2 = 0.f;

    float4 q0buf = __ldg(cp4);
    float4 q1buf = __ldg(cp4 + BB);

#define STEP(CUR, J)                                                        \
    {                                                                       \
        const float cur_ = (CUR);                                           \
        const float pre_ = fmaf(cur_, ca, c0);                              \
        /* ---- th critical path (uses carried M1 = M_1[t-1]) ---- */       \
        const float x_ = fmaf(th, cb, M1 + pre_);                           \
        const float x2_ = x_ * x_;                                          \
        const float u01_ = fmaf(q1, x_, q0);                                \
        const float u34_ = fmaf(q4, x_, q3);                                \
        const float w1s_ = fmaf(q2, x2_, u01_);                             \
        const float x3_ = x_ * x2_;                                         \
        float p_ = fmaf(u34_, x3_, w1s_);                                   \
        p_ = fmaxf(p_, 0.f);                                                \
        const float thn_ = tanh_a(p_);                                      \
        /* ---- reduction M_3[t-1] from state V[t-1] (big slack) ---- */    \
        u64 s_ = fma2_(d3v[1], v[1], mul2_(d3v[0], v[0]));                  \
        float sx_, sy_; upk2(s_, sx_, sy_);                                 \
        const float Wp_ = sx_ + sy_;                                        \
        const float r1_ = Wp_ + __shfl_xor_sync(0xFFFFFFFFu, Wp_, 1);       \
        const float R3_ = r1_ + __shfl_xor_sync(0xFFFFFFFFu, r1_, 2);       \
        /* ---- moment pipeline (uses carried M2 = M_2[t-1]) ---- */        \
        const float M1n_ = M2 + fmaf(th, b1c, cur_ * a1c);                  \
        const float M2n_ = R3_ + fmaf(th, b2c, cur_ * a2c);                 \
        /* ---- state update with OLD th ---- */                            \
        const u64 cur2_ = pk2(cur_, cur_);                                  \
        const u64 th2_  = pk2(th, th);                                      \
        v[0] = fma2_(dv[0], v[0], fma2_(th2_, bv[0], mul2_(cur2_, av[0]))); \
        v[1] = fma2_(dv[1], v[1], fma2_(th2_, bv[1], mul2_(cur2_, av[1]))); \
        M1 = M1n_; M2 = M2n_;                                               \
        if ((J) == sub) outv = MFR * thn_;                                  \
        th = thn_;                                                          \
    }

    for (int tq = 0; tq < TQ; tq += 2) {
        float outv = 0.f;
        {
            const float4 q = q0buf;
            q0buf = __ldg(cp4 + (size_t)(tq + 2) * BB);
            STEP(q.x, 0) STEP(q.y, 1) STEP(q.z, 2) STEP(q.w, 3)
            op[(size_t)tq * (4 * BB)] = outv;
        }
        {
            const float4 q = q1buf;
            q1buf = __ldg(cp4 + (size_t)(tq + 3) * BB);
            STEP(q.x, 0) STEP(q.y, 1) STEP(q.z, 2) STEP(q.w, 3)
            op[(size_t)(tq + 1) * (4 * BB)] = outv;
        }
    }
#undef STEP
}

extern "C" void kernel_launch(void* const* d_in, const int* in_sizes, int n_in,
                              void* d_out, int out_size) {
    const float* currents = (const float*)d_in[0];
    const float* a   = (const float*)d_in[1];
    const float* b   = (const float*)d_in[2];
    const float* pc  = (const float*)d_in[3];
    const float* gb  = (const float*)d_in[4];
    const float* ds  = (const float*)d_in[5];
    const float* mc  = (const float*)d_in[6];
    const float* mfr = (const float*)d_in[7];
    float* out = (float*)d_out;

    dim3 tb(32, 8), tg(TT / 32, BB / 32);
    transpose_kernel<<<tg, tb>>>(currents);
    gfr_kernel<<<(4 * BB) / 128, 128>>>(a, b, pc, gb, ds, mc, mfr, out);
}